// round 3
// baseline (speedup 1.0000x reference)
#include <cuda_runtime.h>
#include <math.h>

// Problem constants
#define BB 32
#define SS 4096
#define HH 1024
#define NSPLIT 32                 // splits of S per batch
#define S_SPLIT (SS / NSPLIT)     // 128 rows per block
#define CHUNK 8                   // rows held in registers per iteration
#define NCHUNK (S_SPLIT / CHUNK)  // 16
#define TPB 256                   // threads per block; each owns 4 h-cols (float4)
#define F4_PER_B (HH / 4)         // 256

// Scratch for split-K partials (no runtime allocation allowed)
__device__ float g_cpart[BB * NSPLIT * HH];   // 4 MiB partial contexts
__device__ float g_m[BB * NSPLIT];
__device__ float g_l[BB * NSPLIT];
__device__ unsigned int g_ticket[BB];         // zero-init; reset by last block

__global__ __launch_bounds__(TPB)
void attn_fused(const float* __restrict__ x, const float* __restrict__ w,
                float* __restrict__ out) {
    const int blk = blockIdx.x;
    const int b   = blk / NSPLIT;
    const int sp  = blk % NSPLIT;
    const int t   = threadIdx.x;
    const int wid = t >> 5;
    const int lane = t & 31;

    const float4* __restrict__ x4 =
        (const float4*)(x + ((size_t)b * SS + (size_t)sp * S_SPLIT) * HH);

    const float4 w4 = ((const float4*)w)[t];

    __shared__ float sred[CHUNK * TPB];   // partial dots, 8 KiB
    __shared__ float se[CHUNK];           // per-row energies
    __shared__ float sp_sh[CHUNK];        // per-row softmax numerators
    __shared__ unsigned int s_islast;

    float4 c = make_float4(0.f, 0.f, 0.f, 0.f);
    float m = -INFINITY;
    float l = 0.f;

    for (int ch = 0; ch < NCHUNK; ch++) {
        const int row0 = ch * CHUNK;
        float4 xr[CHUNK];
        // Streaming loads (no reuse): evict-first; 8 independent LDG.128/thread.
        #pragma unroll
        for (int r = 0; r < CHUNK; r++) {
            xr[r] = __ldcs(&x4[(size_t)(row0 + r) * (HH / 4) + t]);
        }
        #pragma unroll
        for (int r = 0; r < CHUNK; r++) {
            float pd = xr[r].x * w4.x + xr[r].y * w4.y
                     + xr[r].z * w4.z + xr[r].w * w4.w;
            sred[r * TPB + t] = pd;
        }
        __syncthreads();

        // warp `wid` reduces row `wid` (CHUNK == 8 == warps per block)
        {
            const float* rowp = &sred[wid * TPB];
            float s = rowp[lane] + rowp[lane + 32] + rowp[lane + 64] + rowp[lane + 96]
                    + rowp[lane + 128] + rowp[lane + 160] + rowp[lane + 192] + rowp[lane + 224];
            #pragma unroll
            for (int off = 16; off > 0; off >>= 1)
                s += __shfl_xor_sync(0xffffffffu, s, off);
            if (lane == 0) se[wid] = tanhf(s);
        }
        __syncthreads();

        float cmax = se[0];
        #pragma unroll
        for (int r = 1; r < CHUNK; r++) cmax = fmaxf(cmax, se[r]);

        if (cmax > m) {
            const float scale = expf(m - cmax);   // first chunk: expf(-inf)=0
            c.x *= scale; c.y *= scale; c.z *= scale; c.w *= scale;
            l *= scale;
            m = cmax;
        }
        if (t < CHUNK) sp_sh[t] = expf(se[t] - m);
        __syncthreads();

        #pragma unroll
        for (int r = 0; r < CHUNK; r++) {
            const float p = sp_sh[r];
            l   += p;
            c.x += p * xr[r].x;
            c.y += p * xr[r].y;
            c.z += p * xr[r].z;
            c.w += p * xr[r].w;
        }
        __syncthreads();
    }

    // Publish this split's partial
    const int pidx = b * NSPLIT + sp;
    ((float4*)g_cpart)[(size_t)pidx * F4_PER_B + t] = c;
    if (t == 0) { g_m[pidx] = m; g_l[pidx] = l; }

    // Release: make partials visible, then take a ticket for this batch.
    __threadfence();
    if (t == 0) {
        const unsigned int prev = atomicAdd(&g_ticket[b], 1u);
        s_islast = (prev == NSPLIT - 1) ? 1u : 0u;
    }
    __syncthreads();
    if (s_islast == 0) return;

    // ---- Last block of batch b: combine the 32 split partials ----
    __threadfence();  // acquire partner of writers' release

    float M = -INFINITY;
    #pragma unroll
    for (int p = 0; p < NSPLIT; p++) M = fmaxf(M, g_m[b * NSPLIT + p]);

    float L = 0.f;
    float4 acc = make_float4(0.f, 0.f, 0.f, 0.f);
    #pragma unroll
    for (int p = 0; p < NSPLIT; p++) {
        const float sc = expf(g_m[b * NSPLIT + p] - M);
        L += g_l[b * NSPLIT + p] * sc;
        const float4 cp =
            ((const float4*)g_cpart)[(size_t)(b * NSPLIT + p) * F4_PER_B + t];
        acc.x += sc * cp.x;
        acc.y += sc * cp.y;
        acc.z += sc * cp.z;
        acc.w += sc * cp.w;
    }
    const float inv = 1.f / L;
    acc.x *= inv; acc.y *= inv; acc.z *= inv; acc.w *= inv;
    ((float4*)out)[(size_t)b * F4_PER_B + t] = acc;

    // Reset ticket so the next graph replay starts clean.
    if (t == 0) g_ticket[b] = 0u;
}

extern "C" void kernel_launch(void* const* d_in, const int* in_sizes, int n_in,
                              void* d_out, int out_size) {
    const float* x = (const float*)d_in[0];   // [B, S, H] fp32
    const float* w = (const float*)d_in[1];   // [H] fp32
    float* out = (float*)d_out;               // [B, H] fp32
    (void)in_sizes; (void)n_in; (void)out_size;

    attn_fused<<<BB * NSPLIT, TPB>>>(x, w, out);
}

// round 4
// speedup vs baseline: 1.0048x; 1.0048x over previous
#include <cuda_runtime.h>
#include <math.h>

// Problem constants
#define BB 32
#define SS 4096
#define HH 1024
#define NSPLIT 32                 // splits of S per batch
#define S_SPLIT (SS / NSPLIT)     // 128 rows per block
#define CHUNK 8                   // rows held in registers per iteration
#define NCHUNK (S_SPLIT / CHUNK)  // 16
#define TPB 256                   // pass1 threads; each owns 4 h-cols (float4)
#define F4_PER_B (HH / 4)         // 256

// Scratch for split-K partials (no runtime allocation allowed)
__device__ float g_cpart[BB * NSPLIT * HH];   // 4 MiB partial contexts
__device__ float g_m[BB * NSPLIT];
__device__ float g_l[BB * NSPLIT];

__global__ __launch_bounds__(TPB)
void attn_pass1(const float* __restrict__ x, const float* __restrict__ w) {
    const int blk = blockIdx.x;
    const int b   = blk / NSPLIT;
    const int sp  = blk % NSPLIT;
    const int t   = threadIdx.x;
    const int wid = t >> 5;
    const int lane = t & 31;

    const float4* __restrict__ x4 =
        (const float4*)(x + ((size_t)b * SS + (size_t)sp * S_SPLIT) * HH);

    const float4 w4 = ((const float4*)w)[t];

    __shared__ float sred[CHUNK * TPB];   // partial dots, 8 KiB
    __shared__ float se[CHUNK];           // per-row energies
    __shared__ float sp_sh[CHUNK];        // per-row softmax numerators

    float4 c = make_float4(0.f, 0.f, 0.f, 0.f);
    float m = -INFINITY;
    float l = 0.f;

    for (int ch = 0; ch < NCHUNK; ch++) {
        const int row0 = ch * CHUNK;
        float4 xr[CHUNK];
        // Streaming loads (no reuse): evict-first; 8 independent LDG.128/thread.
        #pragma unroll
        for (int r = 0; r < CHUNK; r++) {
            xr[r] = __ldcs(&x4[(size_t)(row0 + r) * (HH / 4) + t]);
        }
        #pragma unroll
        for (int r = 0; r < CHUNK; r++) {
            float pd = xr[r].x * w4.x + xr[r].y * w4.y
                     + xr[r].z * w4.z + xr[r].w * w4.w;
            sred[r * TPB + t] = pd;
        }
        __syncthreads();

        // warp `wid` reduces row `wid` (CHUNK == 8 == warps per block)
        {
            const float* rowp = &sred[wid * TPB];
            float s = rowp[lane] + rowp[lane + 32] + rowp[lane + 64] + rowp[lane + 96]
                    + rowp[lane + 128] + rowp[lane + 160] + rowp[lane + 192] + rowp[lane + 224];
            #pragma unroll
            for (int off = 16; off > 0; off >>= 1)
                s += __shfl_xor_sync(0xffffffffu, s, off);
            if (lane == 0) se[wid] = tanhf(s);
        }
        __syncthreads();

        float cmax = se[0];
        #pragma unroll
        for (int r = 1; r < CHUNK; r++) cmax = fmaxf(cmax, se[r]);

        if (cmax > m) {
            const float scale = expf(m - cmax);   // first chunk: expf(-inf)=0
            c.x *= scale; c.y *= scale; c.z *= scale; c.w *= scale;
            l *= scale;
            m = cmax;
        }
        if (t < CHUNK) sp_sh[t] = expf(se[t] - m);
        __syncthreads();

        #pragma unroll
        for (int r = 0; r < CHUNK; r++) {
            const float p = sp_sh[r];
            l   += p;
            c.x += p * xr[r].x;
            c.y += p * xr[r].y;
            c.z += p * xr[r].z;
            c.w += p * xr[r].w;
        }
        __syncthreads();
    }

    const int pidx = b * NSPLIT + sp;
    ((float4*)g_cpart)[(size_t)pidx * F4_PER_B + t] = c;
    if (t == 0) { g_m[pidx] = m; g_l[pidx] = l; }
}

// ---------------------------------------------------------------------------
// Pass 2: combine the 32 split partials per batch.
// Layout: grid = BB * HCHUNKS (256 blocks), 256 threads.
//   block -> (batch b, h-chunk hc of 32 float4 slices)
//   thread t -> f4local = t & 31, split-group sgrp = t >> 5 (8 groups)
//   each thread reads SPLITS_PER_GRP = 4 partials -> ~16 warps/SM resident,
//   enough in-flight LDG.128 to cover DRAM/L2 latency.
// Scalar M and L are computed redundantly per thread in fixed order
// (64 broadcast loads) -> deterministic. Split-group tree combine in smem
// with fixed order -> deterministic.
// ---------------------------------------------------------------------------
#define HCHUNKS 8
#define F4_PER_CHUNK (F4_PER_B / HCHUNKS)   // 32
#define SGRPS 8
#define SPLITS_PER_GRP (NSPLIT / SGRPS)     // 4

__global__ __launch_bounds__(256)
void attn_pass2(float* __restrict__ out) {
    const int b  = blockIdx.x / HCHUNKS;
    const int hc = blockIdx.x % HCHUNKS;
    const int t  = threadIdx.x;
    const int f4local = t & (F4_PER_CHUNK - 1);
    const int sgrp    = t >> 5;
    const int f4idx   = hc * F4_PER_CHUNK + f4local;

    // Scalar stats: global max and normalizer, fixed order (broadcast loads).
    float M = -INFINITY;
    #pragma unroll
    for (int p = 0; p < NSPLIT; p++) M = fmaxf(M, g_m[b * NSPLIT + p]);
    float L = 0.f;
    #pragma unroll
    for (int p = 0; p < NSPLIT; p++)
        L += g_l[b * NSPLIT + p] * expf(g_m[b * NSPLIT + p] - M);

    // Each thread accumulates its 4 splits (independent LDG.128s).
    float4 acc = make_float4(0.f, 0.f, 0.f, 0.f);
    #pragma unroll
    for (int i = 0; i < SPLITS_PER_GRP; i++) {
        const int p = sgrp * SPLITS_PER_GRP + i;
        const float sc = expf(g_m[b * NSPLIT + p] - M);
        const float4 cp =
            ((const float4*)g_cpart)[(size_t)(b * NSPLIT + p) * F4_PER_B + f4idx];
        acc.x += sc * cp.x;
        acc.y += sc * cp.y;
        acc.z += sc * cp.z;
        acc.w += sc * cp.w;
    }

    // Combine the 8 split-group partials per f4 slice (fixed order).
    __shared__ float4 sacc[SGRPS][F4_PER_CHUNK];
    sacc[sgrp][f4local] = acc;
    __syncthreads();

    if (sgrp == 0) {
        float4 r = sacc[0][f4local];
        #pragma unroll
        for (int g = 1; g < SGRPS; g++) {
            const float4 v = sacc[g][f4local];
            r.x += v.x; r.y += v.y; r.z += v.z; r.w += v.w;
        }
        const float inv = 1.f / L;
        r.x *= inv; r.y *= inv; r.z *= inv; r.w *= inv;
        ((float4*)out)[(size_t)b * F4_PER_B + f4idx] = r;
    }
}

extern "C" void kernel_launch(void* const* d_in, const int* in_sizes, int n_in,
                              void* d_out, int out_size) {
    const float* x = (const float*)d_in[0];   // [B, S, H] fp32
    const float* w = (const float*)d_in[1];   // [H] fp32
    float* out = (float*)d_out;               // [B, H] fp32
    (void)in_sizes; (void)n_in; (void)out_size;

    attn_pass1<<<BB * NSPLIT, TPB>>>(x, w);
    attn_pass2<<<BB * HCHUNKS, 256>>>(out);
}

// round 6
// speedup vs baseline: 1.0497x; 1.0447x over previous
#include <cuda_runtime.h>
#include <math.h>

// Problem constants
#define BB 32
#define SS 4096
#define HH 1024
#define NSPLIT 16                 // splits of S per batch (512 blocks = 1 wave)
#define S_SPLIT (SS / NSPLIT)     // 256 rows per block
#define CHUNK 8                   // rows held in registers per iteration
#define NCHUNK (S_SPLIT / CHUNK)  // 32
#define TPB 256                   // pass1 threads; each owns 4 h-cols (float4)
#define F4_PER_B (HH / 4)         // 256

// Scratch for split-K partials (no runtime allocation allowed)
// NOTE: energy = tanh(.) is in [-1,1], so exp(energy) is in [1/e, e] and no
// max-subtraction is needed anywhere: softmax(e) == exp(e)/sum(exp(e)) exactly.
__device__ float g_cpart[BB * NSPLIT * HH];   // 2 MiB partial contexts
__device__ float g_l[BB * NSPLIT];            // partial normalizers

__global__ __launch_bounds__(TPB)
void attn_pass1(const float* __restrict__ x, const float* __restrict__ w) {
    const int blk = blockIdx.x;
    const int b   = blk / NSPLIT;
    const int sp  = blk % NSPLIT;
    const int t   = threadIdx.x;
    const int wid = t >> 5;
    const int lane = t & 31;

    const float4* __restrict__ x4 =
        (const float4*)(x + ((size_t)b * SS + (size_t)sp * S_SPLIT) * HH);

    const float4 w4 = ((const float4*)w)[t];

    __shared__ float sred[CHUNK * TPB];   // partial dots, 8 KiB
    __shared__ float sp_sh[CHUNK];        // per-row softmax numerators exp(tanh(.))

    float4 c = make_float4(0.f, 0.f, 0.f, 0.f);
    float l = 0.f;

    for (int ch = 0; ch < NCHUNK; ch++) {
        const int row0 = ch * CHUNK;
        float4 xr[CHUNK];
        // Streaming loads (no reuse): evict-first; 8 independent LDG.128/thread.
        #pragma unroll
        for (int r = 0; r < CHUNK; r++) {
            xr[r] = __ldcs(&x4[(size_t)(row0 + r) * (HH / 4) + t]);
        }
        #pragma unroll
        for (int r = 0; r < CHUNK; r++) {
            float pd = xr[r].x * w4.x + xr[r].y * w4.y
                     + xr[r].z * w4.z + xr[r].w * w4.w;
            sred[r * TPB + t] = pd;
        }
        __syncthreads();

        // warp `wid` reduces row `wid` (CHUNK == 8 == warps per block);
        // lane 0 computes p = exp(tanh(s)) directly (no max needed).
        {
            const float* rowp = &sred[wid * TPB];
            float s = rowp[lane] + rowp[lane + 32] + rowp[lane + 64] + rowp[lane + 96]
                    + rowp[lane + 128] + rowp[lane + 160] + rowp[lane + 192] + rowp[lane + 224];
            #pragma unroll
            for (int off = 16; off > 0; off >>= 1)
                s += __shfl_xor_sync(0xffffffffu, s, off);
            if (lane == 0) sp_sh[wid] = expf(tanhf(s));
        }
        __syncthreads();

        #pragma unroll
        for (int r = 0; r < CHUNK; r++) {
            const float p = sp_sh[r];
            l   += p;                      // redundant per-thread, identical value
            c.x += p * xr[r].x;
            c.y += p * xr[r].y;
            c.z += p * xr[r].z;
            c.w += p * xr[r].w;
        }
        __syncthreads();   // protect sred/sp_sh before next chunk
    }

    const int pidx = b * NSPLIT + sp;
    ((float4*)g_cpart)[(size_t)pidx * F4_PER_B + t] = c;
    if (t == 0) g_l[pidx] = l;
}

// ---------------------------------------------------------------------------
// Pass 2: plain fixed-order sum of the 16 split partials per batch, / sum(l).
// grid = BB * HCHUNKS (256 blocks) x 256 threads.
//   thread t -> f4local = t & 31, split-group sgrp = t >> 5 (8 groups x 2 splits)
// No expf, no max: scalar prologue is just 16 broadcast loads.
// ---------------------------------------------------------------------------
#define HCHUNKS 8
#define F4_PER_CHUNK (F4_PER_B / HCHUNKS)   // 32
#define SGRPS 8
#define SPLITS_PER_GRP (NSPLIT / SGRPS)     // 2

__global__ __launch_bounds__(256)
void attn_pass2(float* __restrict__ out) {
    const int b  = blockIdx.x / HCHUNKS;
    const int hc = blockIdx.x % HCHUNKS;
    const int t  = threadIdx.x;
    const int f4local = t & (F4_PER_CHUNK - 1);
    const int sgrp    = t >> 5;
    const int f4idx   = hc * F4_PER_CHUNK + f4local;

    // Normalizer: fixed-order sum of 16 broadcast loads.
    float L = 0.f;
    #pragma unroll
    for (int p = 0; p < NSPLIT; p++) L += g_l[b * NSPLIT + p];

    // Each thread sums its 2 splits (independent LDG.128s).
    float4 acc = make_float4(0.f, 0.f, 0.f, 0.f);
    #pragma unroll
    for (int i = 0; i < SPLITS_PER_GRP; i++) {
        const int p = sgrp * SPLITS_PER_GRP + i;
        const float4 cp =
            ((const float4*)g_cpart)[(size_t)(b * NSPLIT + p) * F4_PER_B + f4idx];
        acc.x += cp.x;
        acc.y += cp.y;
        acc.z += cp.z;
        acc.w += cp.w;
    }

    // Combine the 8 split-group partials per f4 slice (fixed order).
    __shared__ float4 sacc[SGRPS][F4_PER_CHUNK];
    sacc[sgrp][f4local] = acc;
    __syncthreads();

    if (sgrp == 0) {
        float4 r = sacc[0][f4local];
        #pragma unroll
        for (int g = 1; g < SGRPS; g++) {
            const float4 v = sacc[g][f4local];
            r.x += v.x; r.y += v.y; r.z += v.z; r.w += v.w;
        }
        const float inv = 1.f / L;
        r.x *= inv; r.y *= inv; r.z *= inv; r.w *= inv;
        ((float4*)out)[(size_t)b * F4_PER_B + f4idx] = r;
    }
}

extern "C" void kernel_launch(void* const* d_in, const int* in_sizes, int n_in,
                              void* d_out, int out_size) {
    const float* x = (const float*)d_in[0];   // [B, S, H] fp32
    const float* w = (const float*)d_in[1];   // [H] fp32
    float* out = (float*)d_out;               // [B, H] fp32
    (void)in_sizes; (void)n_in; (void)out_size;

    attn_pass1<<<BB * NSPLIT, TPB>>>(x, w);
    attn_pass2<<<BB * HCHUNKS, 256>>>(out);
}